// round 1
// baseline (speedup 1.0000x reference)
#include <cuda_runtime.h>

// ============================================================================
// QCNN 8-qubit circuit — exact algebraic reduction.
//
// The circuit's CNOTs only couple qubit pairs (0,1),(2,3),(4,5),(6,7), which
// are disjoint. All other gates are single-qubit. Hence the state is always a
// tensor product of four 2-qubit states, and <Z_wire0> depends only on the
// (0,1) subsystem. All parameterized gates are batch-independent, so the
// entire 3-layer 2-qubit circuit is one fixed 4x4 complex unitary W.
//
// Per element:  psi0 = (c0c1, c0s1, s0c1, s0s1),  c_w=cos(x_w/2), s_w=sin(x_w/2)
//               phi = W psi0
//               z   = |phi0|^2 + |phi1|^2 - |phi2|^2 - |phi3|^2
//               out = sigmoid(weight * z)
// ============================================================================

// 4x4 complex W, interleaved re/im: g_W[(r*4+c)*2 + {0,1}]
__device__ float g_W[32];

struct Cx { float re, im; };

__device__ __forceinline__ Cx cmul(Cx a, Cx b) {
    return { a.re * b.re - a.im * b.im, a.re * b.im + a.im * b.re };
}

// ----------------------------------------------------------------------------
// Prologue: build W = A3 A2 A1 from params (3,8,3) row-major.
// A_l = CNOT(0->1) * (U_{l,0} (x) U_{l,1}),  U = Rz(g) Ry(b) Rz(a).
// Basis index j = 2*b0 + b1 (wire0 = MSB). CNOT swaps rows 2<->3.
// ----------------------------------------------------------------------------
__global__ void build_W_kernel(const float* __restrict__ params) {
    if (threadIdx.x != 0 || blockIdx.x != 0) return;

    Cx W[4][4];
    #pragma unroll
    for (int r = 0; r < 4; r++)
        #pragma unroll
        for (int c = 0; c < 4; c++)
            W[r][c] = { (r == c) ? 1.0f : 0.0f, 0.0f };

    for (int l = 0; l < 3; l++) {
        // Single-qubit unitaries for wires 0 and 1 of this layer.
        Cx U[2][2][2];  // U[w][row][col]
        for (int w = 0; w < 2; w++) {
            float a = params[(l * 8 + w) * 3 + 0];
            float b = params[(l * 8 + w) * 3 + 1];
            float g = params[(l * 8 + w) * 3 + 2];
            float sb, cb;  sincosf(0.5f * b, &sb, &cb);
            float apg = 0.5f * (a + g);
            float amg = 0.5f * (a - g);
            float sp, cp;  sincosf(apg, &sp, &cp);
            float sm, cm;  sincosf(amg, &sm, &cm);
            // U00 = cb e^{-i(a+g)/2}   U01 = -sb e^{+i(a-g)/2}
            // U10 = sb e^{-i(a-g)/2}   U11 =  cb e^{+i(a+g)/2}
            U[w][0][0] = {  cb * cp, -cb * sp };
            U[w][0][1] = { -sb * cm, -sb * sm };
            U[w][1][0] = {  sb * cm, -sb * sm };
            U[w][1][1] = {  cb * cp,  cb * sp };
        }

        // K = U0 (x) U1 : K[2b0+b1][2b0'+b1'] = U0[b0][b0'] * U1[b1][b1']
        Cx K[4][4];
        #pragma unroll
        for (int r = 0; r < 4; r++)
            #pragma unroll
            for (int c = 0; c < 4; c++)
                K[r][c] = cmul(U[0][r >> 1][c >> 1], U[1][r & 1][c & 1]);

        // T = K * W
        Cx T[4][4];
        #pragma unroll
        for (int r = 0; r < 4; r++)
            #pragma unroll
            for (int c = 0; c < 4; c++) {
                Cx acc = { 0.0f, 0.0f };
                #pragma unroll
                for (int k = 0; k < 4; k++) {
                    Cx p = cmul(K[r][k], W[k][c]);
                    acc.re += p.re;  acc.im += p.im;
                }
                T[r][c] = acc;
            }

        // CNOT(ctrl=wire0, tgt=wire1): swap basis states |10> <-> |11>,
        // i.e. rows 2 and 3.
        #pragma unroll
        for (int c = 0; c < 4; c++) {
            W[0][c] = T[0][c];
            W[1][c] = T[1][c];
            W[2][c] = T[3][c];
            W[3][c] = T[2][c];
        }
    }

    #pragma unroll
    for (int r = 0; r < 4; r++)
        #pragma unroll
        for (int c = 0; c < 4; c++) {
            g_W[(r * 4 + c) * 2 + 0] = W[r][c].re;
            g_W[(r * 4 + c) * 2 + 1] = W[r][c].im;
        }
}

// ----------------------------------------------------------------------------
// Main: one thread per batch element.
// ----------------------------------------------------------------------------
__global__ void qcnn_main_kernel(const float* __restrict__ x,
                                 const float* __restrict__ weight,
                                 float* __restrict__ out,
                                 int n) {
    int i = blockIdx.x * blockDim.x + threadIdx.x;
    if (i >= n) return;

    // x row i is 32 bytes, 32B-aligned; we need elements 0 and 1.
    float2 xv = *reinterpret_cast<const float2*>(x + (size_t)i * 8);

    float s0, c0, s1, c1;
    sincosf(0.5f * xv.x, &s0, &c0);
    sincosf(0.5f * xv.y, &s1, &c1);

    float psi[4] = { c0 * c1, c0 * s1, s0 * c1, s0 * s1 };

    float z = 0.0f;
    #pragma unroll
    for (int r = 0; r < 4; r++) {
        float re = 0.0f, im = 0.0f;
        #pragma unroll
        for (int c = 0; c < 4; c++) {
            re = fmaf(g_W[(r * 4 + c) * 2 + 0], psi[c], re);
            im = fmaf(g_W[(r * 4 + c) * 2 + 1], psi[c], im);
        }
        float p = fmaf(re, re, im * im);
        z += (r < 2) ? p : -p;
    }

    float w = weight[0];
    out[i] = 1.0f / (1.0f + expf(-w * z));
}

// ----------------------------------------------------------------------------
// Launch contract
// ----------------------------------------------------------------------------
extern "C" void kernel_launch(void* const* d_in, const int* in_sizes, int n_in,
                              void* d_out, int out_size) {
    const float* x      = (const float*)d_in[0];   // (65536, 8) fp32
    const float* params = (const float*)d_in[1];   // (3, 8, 3) fp32
    const float* weight = (const float*)d_in[2];   // scalar fp32
    float* out = (float*)d_out;                    // (65536,) fp32

    int n = in_sizes[0] / 8;

    build_W_kernel<<<1, 32>>>(params);

    int threads = 256;
    int blocks = (n + threads - 1) / threads;
    qcnn_main_kernel<<<blocks, threads>>>(x, weight, out, n);
}

// round 2
// speedup vs baseline: 1.4923x; 1.4923x over previous
#include <cuda_runtime.h>

// ============================================================================
// QCNN 8-qubit circuit — exact algebraic reduction, single fused kernel.
//
// CNOTs only couple disjoint qubit pairs (0,1),(2,3),(4,5),(6,7); <Z_0>
// depends only on the (0,1) 2-qubit subsystem. All parameterized gates are
// batch-independent, so the 3-layer 2-qubit circuit is one fixed 4x4 complex
// unitary W, built once per block (warp-cooperative, hidden behind the x-load
// latency), then applied per batch element:
//
//   psi0 = (c0c1, c0s1, s0c1, s0s1),  c_w=cos(x_w/2), s_w=sin(x_w/2)
//   phi  = W psi0
//   z    = |phi0|^2 + |phi1|^2 - |phi2|^2 - |phi3|^2
//   out  = sigmoid(weight * z)
// ============================================================================

struct Cx { float re, im; };

__device__ __forceinline__ Cx cmul(Cx a, Cx b) {
    return { a.re * b.re - a.im * b.im, a.re * b.im + a.im * b.re };
}

// Warp-cooperative W build: lanes 0..15 each own element (r,c), r=lane>>2,
// c=lane&3. Layer update T = CNOT * (U0 (x) U1) * W done with shuffles.
// All 32 lanes execute (16..31 compute garbage); only 0..15 write smem.
__device__ __forceinline__ void build_W(const float* __restrict__ params,
                                        float* __restrict__ sW) {
    const unsigned FULL = 0xFFFFFFFFu;
    int lane = threadIdx.x & 31;
    int r = (lane >> 2) & 3;
    int c = lane & 3;

    Cx w = { (r == c) ? 1.0f : 0.0f, 0.0f };

    #pragma unroll
    for (int l = 0; l < 3; l++) {
        // Single-qubit unitaries U[w] = Rz(g) Ry(b) Rz(a), computed
        // redundantly by every lane.
        Cx U[2][2][2];
        #pragma unroll
        for (int q = 0; q < 2; q++) {
            float a = params[(l * 8 + q) * 3 + 0];
            float b = params[(l * 8 + q) * 3 + 1];
            float g = params[(l * 8 + q) * 3 + 2];
            float sb, cb;  __sincosf(0.5f * b, &sb, &cb);
            float sp, cp;  __sincosf(0.5f * (a + g), &sp, &cp);
            float sm, cm;  __sincosf(0.5f * (a - g), &sm, &cm);
            U[q][0][0] = {  cb * cp, -cb * sp };
            U[q][0][1] = { -sb * cm, -sb * sm };
            U[q][1][0] = {  sb * cm, -sb * sm };
            U[q][1][1] = {  cb * cp,  cb * sp };
        }

        // K row r of (U0 (x) U1): K[r][k] = U0[r>>1][k>>1] * U1[r&1][k&1]
        Cx K[4];
        #pragma unroll
        for (int k = 0; k < 4; k++)
            K[k] = cmul(U[0][r >> 1][k >> 1], U[1][r & 1][k & 1]);

        // T[r][c] = sum_k K[r][k] * W[k][c]; W[k][c] lives in lane k*4+c.
        Cx acc = { 0.0f, 0.0f };
        #pragma unroll
        for (int k = 0; k < 4; k++) {
            Cx wk;
            wk.re = __shfl_sync(FULL, w.re, k * 4 + c);
            wk.im = __shfl_sync(FULL, w.im, k * 4 + c);
            Cx p = cmul(K[k], wk);
            acc.re += p.re;  acc.im += p.im;
        }

        // CNOT(wire0 -> wire1): swap rows 2<->3. New W[r][c] = T[sw(r)][c],
        // which lives in lane sw(r)*4+c.
        int sr = (r >= 2) ? (5 - r) : r;   // 0,1,3,2
        w.re = __shfl_sync(FULL, acc.re, sr * 4 + c);
        w.im = __shfl_sync(FULL, acc.im, sr * 4 + c);
    }

    if (lane < 16) {
        sW[lane * 2 + 0] = w.re;
        sW[lane * 2 + 1] = w.im;
    }
}

__global__ void __launch_bounds__(128) qcnn_fused_kernel(
    const float* __restrict__ x,
    const float* __restrict__ params,
    const float* __restrict__ weight,
    float* __restrict__ out,
    int n)
{
    __shared__ float sW[33];   // 32 W entries + weight

    int i = blockIdx.x * blockDim.x + threadIdx.x;

    // Issue the global load FIRST so its latency overlaps the W build.
    float2 xv = make_float2(0.0f, 0.0f);
    if (i < n)
        xv = *reinterpret_cast<const float2*>(x + (size_t)i * 8);

    if (threadIdx.x < 32) {
        build_W(params, sW);
        if (threadIdx.x == 0) sW[32] = weight[0];
    }

    // Independent of W: compute initial product state while warp 0 builds W.
    float s0, c0, s1, c1;
    __sincosf(0.5f * xv.x, &s0, &c0);
    __sincosf(0.5f * xv.y, &s1, &c1);
    float psi[4] = { c0 * c1, c0 * s1, s0 * c1, s0 * s1 };

    __syncthreads();

    if (i >= n) return;

    float z = 0.0f;
    #pragma unroll
    for (int r = 0; r < 4; r++) {
        float re = 0.0f, im = 0.0f;
        #pragma unroll
        for (int c = 0; c < 4; c++) {
            re = fmaf(sW[(r * 4 + c) * 2 + 0], psi[c], re);
            im = fmaf(sW[(r * 4 + c) * 2 + 1], psi[c], im);
        }
        float p = fmaf(re, re, im * im);
        z += (r < 2) ? p : -p;
    }

    float t = sW[32] * z;
    out[i] = __fdividef(1.0f, 1.0f + __expf(-t));
}

extern "C" void kernel_launch(void* const* d_in, const int* in_sizes, int n_in,
                              void* d_out, int out_size) {
    const float* x      = (const float*)d_in[0];   // (65536, 8) fp32
    const float* params = (const float*)d_in[1];   // (3, 8, 3) fp32
    const float* weight = (const float*)d_in[2];   // scalar fp32
    float* out = (float*)d_out;                    // (65536,) fp32

    int n = in_sizes[0] / 8;

    int threads = 128;
    int blocks = (n + threads - 1) / threads;      // 512 blocks
    qcnn_fused_kernel<<<blocks, threads>>>(x, params, weight, out, n);
}